// round 4
// baseline (speedup 1.0000x reference)
#include <cuda_runtime.h>
#include <math.h>

// Problem constants (from reference)
#define B_   4
#define H_   704
#define W_   704
#define HW_  495616u                 // H*W, fits easily in 32 bits
#define M_   32
#define P_   128
#define NN_  129
#define GAIN_ 2.0f
#define TWO_PI_ 6.2831853071795864769f

// Work decomposition: one item per thread, one warp per block, one block per SM.
// Remapped so every warp is branch-uniform:
//   items [0,128)    -> positive classification   (blocks 0-3)
//   items [128,256)  -> negative classification 0..127 (blocks 4-7)
//   items [256,320)  -> regression (m,k): i-256 -> m=(i-256)>>1, k=(i-256)&1 (blocks 8-9)
//   item  320        -> negative classification 128 (block 10, lane 0)
#define N_ITEMS   321
#define THREADS_  32
#define N_BLOCKS  ((N_ITEMS + THREADS_ - 1) / THREADS_)   // 11

__device__ float g_partial[N_BLOCKS];
__device__ int   g_ticket = 0;

__device__ __forceinline__ float softplus(float x) {
    float ax = fabsf(x);
    return fmaxf(x, 0.0f) + __logf(1.0f + __expf(-ax));
}

__device__ __forceinline__ float smooth_l1(float d) {
    float a = fabsf(d);
    return (a < 1.0f) ? 0.5f * d * d : a - 0.5f;
}

__global__ void __launch_bounds__(THREADS_, 1)
loss_total_kernel(const float* __restrict__ rb,      // ref_boxes, batch 3  [M,7]
                  const float* __restrict__ pc,      // pred_class, batch 3 [4,H,W]
                  const float* __restrict__ pr,      // pred_regress, batch 3 [14,H,W]
                  const float* __restrict__ anchor,  // [2,7,H,W]
                  const int2*  __restrict__ pidx,    // batch 3 [P]
                  const int2*  __restrict__ nidx,    // batch 3 [NN]
                  const int2*  __restrict__ ridx,    // batch 3 [M] (R=1)
                  float* __restrict__ out) {
    const int item = blockIdx.x * THREADS_ + threadIdx.x;

    float contrib = 0.0f;

    // classification item? (pos, neg 0..127, or the straggler neg 128)
    bool is_pos      = (item < P_);
    bool is_neg      = (item >= P_ && item < 256) || (item == 320);
    bool is_reg      = (item >= 256 && item < 320);

    if (is_pos || is_neg) {
        int2 yx;
        float inv_n;
        if (is_pos) {
            yx = __ldg(&pidx[item]);
            inv_n = 1.0f / (float)P_;
        } else {
            int j = (item == 320) ? 128 : (item - P_);
            yx = __ldg(&nidx[j]);
            inv_n = 1.0f / (float)NN_;
        }
        unsigned off = (unsigned)yx.x * W_ + (unsigned)yx.y;
        float l0 = __ldg(pc + off);
        float l1 = __ldg(pc + HW_ + off);
        float l2 = __ldg(pc + 2u * HW_ + off);
        float l3 = __ldg(pc + 3u * HW_ + off);
        float s;
        if (is_pos) {
            // label 1: lse(l0,l1) - l1 = softplus(l0 - l1)
            s = softplus(l0 - l1) + softplus(l2 - l3);
        } else {
            // label 0: lse(l0,l1) - l0 = softplus(l1 - l0)
            s = softplus(l1 - l0) + softplus(l3 - l2);
        }
        contrib = s * inv_n;
    } else if (is_reg) {
        int i = item - 256;
        int m = i >> 1, k = i & 1;
        int2 yx = __ldg(&ridx[m]);
        unsigned off = (unsigned)yx.x * W_ + (unsigned)yx.y;
        unsigned cbase = (unsigned)(k * 7) * HW_ + off;

        float a[7], p[7], rf[7];
        #pragma unroll
        for (int j = 0; j < 7; j++)
            a[j] = __ldg(anchor + cbase + (unsigned)j * HW_);
        #pragma unroll
        for (int j = 0; j < 7; j++)
            p[j] = __ldg(pr + cbase + (unsigned)j * HW_);
        #pragma unroll
        for (int j = 0; j < 7; j++)
            rf[j] = __ldg(rb + m * 7 + j);

        float inv_diag = rsqrtf(a[3] * a[3] + a[4] * a[4]);
        float ov0 = (rf[0] - a[0]) * inv_diag;
        float ov1 = (rf[1] - a[1]) * inv_diag;
        float ov2 = __fdividef(rf[2] - a[2], a[5]);
        float ov3 = __logf(__fdividef(rf[3], a[3]));
        float ov4 = __logf(__fdividef(rf[4], a[4]));
        float ov5 = __logf(__fdividef(rf[5], a[5]));
        float dth = rf[6] - a[6];
        // atan2(sin d, cos d) == wrap d into (-pi, pi]
        float ov6 = dth - TWO_PI_ * rintf(dth * (1.0f / TWO_PI_));

        float s  = smooth_l1(p[0] - ov0);
        s += smooth_l1(p[1] - ov1);
        s += smooth_l1(p[2] - ov2);
        s += smooth_l1(p[3] - ov3);
        s += smooth_l1(p[4] - ov4);
        s += smooth_l1(p[5] - ov5);
        s += smooth_l1(p[6] - ov6);
        contrib = s * (GAIN_ / 14.0f);
    }

    // ---- warp reduction (single warp per block) ----
    const unsigned FULL = 0xFFFFFFFFu;
    #pragma unroll
    for (int o = 16; o > 0; o >>= 1)
        contrib += __shfl_down_sync(FULL, contrib, o);

    if (threadIdx.x == 0) {
        g_partial[blockIdx.x] = contrib;
        __threadfence();
        int ticket = atomicAdd(&g_ticket, 1);
        if (ticket == N_BLOCKS - 1) {
            // last-arriving block finalizes; partials are L2-visible after fences
            float total = 0.0f;
            #pragma unroll
            for (int w = 0; w < N_BLOCKS; w++)
                total += __ldcg(&g_partial[w]);
            out[0] = total;
            g_ticket = 0;   // reset so graph replays are deterministic
        }
    }
}

extern "C" void kernel_launch(void* const* d_in, const int* in_sizes, int n_in,
                              void* d_out, int out_size) {
    const int b = B_ - 1;  // reference returns losses[-1] only
    const float* ref_boxes    = (const float*)d_in[0] + (size_t)b * M_ * 7;
    const float* pred_class   = (const float*)d_in[1] + (size_t)b * 4  * HW_;
    const float* pred_regress = (const float*)d_in[2] + (size_t)b * 14 * HW_;
    const float* anchor       = (const float*)d_in[3];
    const int2*  pos_idx      = (const int2*)((const int*)d_in[4] + b * P_ * 2);
    const int2*  neg_idx      = (const int2*)((const int*)d_in[5] + b * NN_ * 2);
    const int2*  reg_idx      = (const int2*)((const int*)d_in[6] + b * M_ * 2);
    float* out = (float*)d_out;

    loss_total_kernel<<<N_BLOCKS, THREADS_>>>(ref_boxes, pred_class, pred_regress,
                                              anchor, pos_idx, neg_idx, reg_idx, out);
}

// round 5
// speedup vs baseline: 1.0047x; 1.0047x over previous
#include <cuda_runtime.h>
#include <math.h>

// Problem constants (from reference)
#define B_   4
#define H_   704
#define W_   704
#define HW_  495616u                 // H*W
#define M_   32
#define P_   128
#define NN_  129
#define GAIN_ 2.0f
#define TWO_PI_ 6.2831853071795864769f

// Work decomposition (one item per thread, one warp per block):
//   items [0,128)   -> positive classification
//   items [128,257) -> negative classification (129)
//   items [257,321) -> regression (m,k) pairs: i=item-257, m=i>>1, k=i&1
#define N_ITEMS   321
#define THREADS_  32
#define N_BLOCKS  ((N_ITEMS + THREADS_ - 1) / THREADS_)   // 11

__device__ float g_partial[12];      // 11 used, padded to 12 for float4 reads
__device__ int   g_ticket = 0;

__device__ __forceinline__ float softplus(float x) {
    float ax = fabsf(x);
    return fmaxf(x, 0.0f) + __logf(1.0f + __expf(-ax));
}

__device__ __forceinline__ float smooth_l1(float d) {
    float a = fabsf(d);
    return (a < 1.0f) ? 0.5f * d * d : a - 0.5f;
}

__global__ void __launch_bounds__(THREADS_, 1)
loss_total_kernel(const float* __restrict__ rb,      // ref_boxes (batch 3)  [M,7]
                  const float* __restrict__ pc,      // pred_class (batch 3) [4,H,W]
                  const float* __restrict__ pr,      // pred_regress (batch 3) [14,H,W]
                  const float* __restrict__ anchor,  // [2,7,H,W]
                  const int2*  __restrict__ pidx,    // (batch 3) [P]
                  const int2*  __restrict__ nidx,    // (batch 3) [NN]
                  const int2*  __restrict__ ridx,    // (batch 3) [M]  (R=1)
                  float* __restrict__ out) {
    const int item = blockIdx.x * THREADS_ + threadIdx.x;

    float contrib = 0.0f;

    if (item < P_) {
        // ---- positive classification ----
        int2 yx = __ldg(&pidx[item]);
        unsigned off = (unsigned)yx.x * W_ + (unsigned)yx.y;
        float l0 = __ldg(pc + off);
        float l1 = __ldg(pc + HW_ + off);
        float l2 = __ldg(pc + 2u * HW_ + off);
        float l3 = __ldg(pc + 3u * HW_ + off);
        // label 1: lse(l0,l1) - l1 = softplus(l0 - l1)
        contrib = (softplus(l0 - l1) + softplus(l2 - l3)) * (1.0f / (float)P_);
    } else if (item < P_ + NN_) {
        // ---- negative classification ----
        int2 yx = __ldg(&nidx[item - P_]);
        unsigned off = (unsigned)yx.x * W_ + (unsigned)yx.y;
        float l0 = __ldg(pc + off);
        float l1 = __ldg(pc + HW_ + off);
        float l2 = __ldg(pc + 2u * HW_ + off);
        float l3 = __ldg(pc + 3u * HW_ + off);
        // label 0: lse(l0,l1) - l0 = softplus(l1 - l0)
        contrib = (softplus(l1 - l0) + softplus(l3 - l2)) * (1.0f / (float)NN_);
    } else if (item < N_ITEMS) {
        // ---- regression (m, k) ----
        int i = item - (P_ + NN_);
        int m = i >> 1, k = i & 1;
        int2 yx = __ldg(&ridx[m]);
        unsigned off = (unsigned)yx.x * W_ + (unsigned)yx.y;
        unsigned cbase = (unsigned)(k * 7) * HW_ + off;

        float a[7], p[7], rf[7];
        #pragma unroll
        for (int j = 0; j < 7; j++)
            a[j] = __ldg(anchor + cbase + (unsigned)j * HW_);
        #pragma unroll
        for (int j = 0; j < 7; j++)
            p[j] = __ldg(pr + cbase + (unsigned)j * HW_);
        #pragma unroll
        for (int j = 0; j < 7; j++)
            rf[j] = __ldg(rb + m * 7 + j);

        float inv_diag = rsqrtf(a[3] * a[3] + a[4] * a[4]);
        float ov0 = (rf[0] - a[0]) * inv_diag;
        float ov1 = (rf[1] - a[1]) * inv_diag;
        float ov2 = __fdividef(rf[2] - a[2], a[5]);
        float ov3 = __logf(__fdividef(rf[3], a[3]));
        float ov4 = __logf(__fdividef(rf[4], a[4]));
        float ov5 = __logf(__fdividef(rf[5], a[5]));
        float dth = rf[6] - a[6];
        // atan2(sin d, cos d) == wrap d into (-pi, pi]
        float ov6 = dth - TWO_PI_ * rintf(dth * (1.0f / TWO_PI_));

        float s  = smooth_l1(p[0] - ov0);
        s += smooth_l1(p[1] - ov1);
        s += smooth_l1(p[2] - ov2);
        s += smooth_l1(p[3] - ov3);
        s += smooth_l1(p[4] - ov4);
        s += smooth_l1(p[5] - ov5);
        s += smooth_l1(p[6] - ov6);
        contrib = s * (GAIN_ / 14.0f);
    }

    // ---- warp reduction (single warp per block) ----
    const unsigned FULL = 0xFFFFFFFFu;
    #pragma unroll
    for (int o = 16; o > 0; o >>= 1)
        contrib += __shfl_down_sync(FULL, contrib, o);

    if (threadIdx.x == 0) {
        __stcg(&g_partial[blockIdx.x], contrib);   // straight to L2
        // Fused release-acquire ticket: release orders the partial store above;
        // acquire (for the winning block) makes all other partials visible.
        int ticket;
        asm volatile("atom.acq_rel.gpu.global.add.s32 %0, [%1], 1;"
                     : "=r"(ticket) : "l"(&g_ticket) : "memory");
        if (ticket == N_BLOCKS - 1) {
            // last-arriving block finalizes; vectorized partial collection
            const float4* p4 = (const float4*)g_partial;
            float4 v0 = __ldcg(&p4[0]);
            float4 v1 = __ldcg(&p4[1]);
            float4 v2 = __ldcg(&p4[2]);
            float total = ((v0.x + v0.y) + (v0.z + v0.w))
                        + ((v1.x + v1.y) + (v1.z + v1.w))
                        + ((v2.x + v2.y) + v2.z);   // slot 11 is padding
            out[0] = total;
            g_ticket = 0;   // reset so graph replays are deterministic
        }
    }
}

extern "C" void kernel_launch(void* const* d_in, const int* in_sizes, int n_in,
                              void* d_out, int out_size) {
    const int b = B_ - 1;  // reference returns losses[-1] only
    const float* ref_boxes    = (const float*)d_in[0] + (size_t)b * M_ * 7;
    const float* pred_class   = (const float*)d_in[1] + (size_t)b * 4  * HW_;
    const float* pred_regress = (const float*)d_in[2] + (size_t)b * 14 * HW_;
    const float* anchor       = (const float*)d_in[3];
    const int2*  pos_idx      = (const int2*)((const int*)d_in[4] + b * P_ * 2);
    const int2*  neg_idx      = (const int2*)((const int*)d_in[5] + b * NN_ * 2);
    const int2*  reg_idx      = (const int2*)((const int*)d_in[6] + b * M_ * 2);
    float* out = (float*)d_out;

    loss_total_kernel<<<N_BLOCKS, THREADS_>>>(ref_boxes, pred_class, pred_regress,
                                              anchor, pos_idx, neg_idx, reg_idx, out);
}

// round 7
// speedup vs baseline: 1.0385x; 1.0337x over previous
#include <cuda_runtime.h>
#include <math.h>

// Problem constants (from reference)
#define B_   4
#define H_   704
#define W_   704
#define HW_  495616u                 // H*W
#define M_   32
#define P_   128
#define NN_  129
#define GAIN_ 2.0f
#define TWO_PI_ 6.2831853071795864769f

// Work decomposition (one item per thread, one warp per block):
//   items [0,128)   -> positive classification
//   items [128,257) -> negative classification (129)
//   items [257,321) -> regression (m,k) pairs: i=item-257, m=i>>1, k=i&1
#define N_ITEMS   321
#define THREADS_  32
#define N_BLOCKS  ((N_ITEMS + THREADS_ - 1) / THREADS_)   // 11

__device__ float g_acc    = 0.0f;
__device__ int   g_ticket = 0;

__device__ __forceinline__ float softplus(float x) {
    float ax = fabsf(x);
    return fmaxf(x, 0.0f) + __logf(1.0f + __expf(-ax));
}

__device__ __forceinline__ float smooth_l1(float d) {
    float a = fabsf(d);
    return (a < 1.0f) ? 0.5f * d * d : a - 0.5f;
}

__global__ void __launch_bounds__(THREADS_, 1)
loss_total_kernel(const float* __restrict__ rb,      // ref_boxes (batch 3)  [M,7]
                  const float* __restrict__ pc,      // pred_class (batch 3) [4,H,W]
                  const float* __restrict__ pr,      // pred_regress (batch 3) [14,H,W]
                  const float* __restrict__ anchor,  // [2,7,H,W]
                  const int2*  __restrict__ pidx,    // (batch 3) [P]
                  const int2*  __restrict__ nidx,    // (batch 3) [NN]
                  const int2*  __restrict__ ridx,    // (batch 3) [M]  (R=1)
                  float* __restrict__ out) {
    const int item = blockIdx.x * THREADS_ + threadIdx.x;

    float contrib = 0.0f;

    if (item < P_) {
        // ---- positive classification ----
        int2 yx = __ldg(&pidx[item]);
        unsigned off = (unsigned)yx.x * W_ + (unsigned)yx.y;
        float l0 = __ldg(pc + off);
        float l1 = __ldg(pc + HW_ + off);
        float l2 = __ldg(pc + 2u * HW_ + off);
        float l3 = __ldg(pc + 3u * HW_ + off);
        // label 1: lse(l0,l1) - l1 = softplus(l0 - l1)
        contrib = (softplus(l0 - l1) + softplus(l2 - l3)) * (1.0f / (float)P_);
    } else if (item < P_ + NN_) {
        // ---- negative classification ----
        int2 yx = __ldg(&nidx[item - P_]);
        unsigned off = (unsigned)yx.x * W_ + (unsigned)yx.y;
        float l0 = __ldg(pc + off);
        float l1 = __ldg(pc + HW_ + off);
        float l2 = __ldg(pc + 2u * HW_ + off);
        float l3 = __ldg(pc + 3u * HW_ + off);
        // label 0: lse(l0,l1) - l0 = softplus(l1 - l0)
        contrib = (softplus(l1 - l0) + softplus(l3 - l2)) * (1.0f / (float)NN_);
    } else if (item < N_ITEMS) {
        // ---- regression (m, k) ----
        int i = item - (P_ + NN_);
        int m = i >> 1, k = i & 1;
        int2 yx = __ldg(&ridx[m]);
        unsigned off = (unsigned)yx.x * W_ + (unsigned)yx.y;
        unsigned cbase = (unsigned)(k * 7) * HW_ + off;

        float a[7], p[7], rf[7];
        #pragma unroll
        for (int j = 0; j < 7; j++)
            a[j] = __ldg(anchor + cbase + (unsigned)j * HW_);
        #pragma unroll
        for (int j = 0; j < 7; j++)
            p[j] = __ldg(pr + cbase + (unsigned)j * HW_);
        #pragma unroll
        for (int j = 0; j < 7; j++)
            rf[j] = __ldg(rb + m * 7 + j);

        float inv_diag = rsqrtf(a[3] * a[3] + a[4] * a[4]);
        float ov0 = (rf[0] - a[0]) * inv_diag;
        float ov1 = (rf[1] - a[1]) * inv_diag;
        float ov2 = __fdividef(rf[2] - a[2], a[5]);
        float ov3 = __logf(__fdividef(rf[3], a[3]));
        float ov4 = __logf(__fdividef(rf[4], a[4]));
        float ov5 = __logf(__fdividef(rf[5], a[5]));
        float dth = rf[6] - a[6];
        // atan2(sin d, cos d) == wrap d into (-pi, pi]
        float ov6 = dth - TWO_PI_ * rintf(dth * (1.0f / TWO_PI_));

        float s  = smooth_l1(p[0] - ov0);
        s += smooth_l1(p[1] - ov1);
        s += smooth_l1(p[2] - ov2);
        s += smooth_l1(p[3] - ov3);
        s += smooth_l1(p[4] - ov4);
        s += smooth_l1(p[5] - ov5);
        s += smooth_l1(p[6] - ov6);
        contrib = s * (GAIN_ / 14.0f);
    }

    // ---- warp reduction (single warp per block) ----
    const unsigned FULL = 0xFFFFFFFFu;
    #pragma unroll
    for (int o = 16; o > 0; o >>= 1)
        contrib += __shfl_down_sync(FULL, contrib, o);

    if (threadIdx.x == 0) {
        // No-return float accumulation (REDG) — off the critical path.
        atomicAdd(&g_acc, contrib);
        // Fused release-acquire ticket: release orders the REDG above;
        // acquire (for the last block) makes all accumulations visible.
        int ticket;
        asm volatile("atom.acq_rel.gpu.global.add.s32 %0, [%1], 1;"
                     : "=r"(ticket) : "l"(&g_ticket) : "memory");
        if (ticket == N_BLOCKS - 1) {
            float total = __ldcg(&g_acc);
            out[0] = total;
            // Reset scratch for the next (graph-replayed) launch. Safe: the
            // next launch cannot begin until this kernel fully drains.
            __stcg(&g_acc, 0.0f);
            g_ticket = 0;
        }
    }
}

extern "C" void kernel_launch(void* const* d_in, const int* in_sizes, int n_in,
                              void* d_out, int out_size) {
    const int b = B_ - 1;  // reference returns losses[-1] only
    const float* ref_boxes    = (const float*)d_in[0] + (size_t)b * M_ * 7;
    const float* pred_class   = (const float*)d_in[1] + (size_t)b * 4  * HW_;
    const float* pred_regress = (const float*)d_in[2] + (size_t)b * 14 * HW_;
    const float* anchor       = (const float*)d_in[3];
    const int2*  pos_idx      = (const int2*)((const int*)d_in[4] + b * P_ * 2);
    const int2*  neg_idx      = (const int2*)((const int*)d_in[5] + b * NN_ * 2);
    const int2*  reg_idx      = (const int2*)((const int*)d_in[6] + b * M_ * 2);
    float* out = (float*)d_out;

    loss_total_kernel<<<N_BLOCKS, THREADS_>>>(ref_boxes, pred_class, pred_regress,
                                              anchor, pos_idx, neg_idx, reg_idx, out);
}